// round 1
// baseline (speedup 1.0000x reference)
#include <cuda_runtime.h>
#include <math.h>
#include <float.h>

#define NV 100000
#define EV 1600000
#define ET 1700000   // EV + NV self loops

// ---------------- scratch (static device globals; no allocation) ----------------
__device__ int    g_deg[NV];
__device__ float  g_dinv[NV];
__device__ int    g_rowptr[NV + 1];
__device__ int    g_cursor[NV];
__device__ int    g_bsum[128];
__device__ int    g_col[ET];
__device__ float  g_nrm[ET];
__device__ float4 g_hA[NV * 32];    // [N,128] ping
__device__ float4 g_hB[NV * 32];    // [N,128] pong
__device__ float4 g_acc[NV * 32];   // diffusion accumulator [N,128]
__device__ float4 g_h1[NV * 16];    // [N,64]
__device__ float  g_als1[NV * 8];
__device__ float  g_ald1[NV * 8];
__device__ float4 g_act1[NV * 16];  // [N,64] after ELU
__device__ float  g_h2[NV * 40];
__device__ float  g_als2[NV];
__device__ float  g_ald2[NV];

// ---------------- CSR construction ----------------
__global__ void k_zero_deg() {
    int i = blockIdx.x * blockDim.x + threadIdx.x;
    if (i < NV) g_deg[i] = 0;
}

__global__ void k_count(const int* __restrict__ ei) {
    int stride = gridDim.x * blockDim.x;
    for (int i = blockIdx.x * blockDim.x + threadIdx.x; i < EV; i += stride)
        atomicAdd(&g_deg[ei[EV + i]], 1);
}

__global__ void k_finish_deg() {
    int i = blockIdx.x * blockDim.x + threadIdx.x;
    if (i < NV) {
        int d = g_deg[i] + 1;  // + self loop
        g_deg[i] = d;
        g_dinv[i] = rsqrtf((float)d);
    }
}

__global__ __launch_bounds__(1024) void k_scan1() {
    __shared__ int sh[1024];
    int i = blockIdx.x * 1024 + threadIdx.x;
    int v = (i < NV) ? g_deg[i] : 0;
    sh[threadIdx.x] = v;
    __syncthreads();
    for (int off = 1; off < 1024; off <<= 1) {
        int tv = (threadIdx.x >= off) ? sh[threadIdx.x - off] : 0;
        __syncthreads();
        sh[threadIdx.x] += tv;
        __syncthreads();
    }
    if (i < NV) g_rowptr[i] = sh[threadIdx.x] - v;   // exclusive, block-local
    if (threadIdx.x == 1023) g_bsum[blockIdx.x] = sh[1023];
}

__global__ void k_scan2(int nb) {
    if (threadIdx.x == 0) {
        int s = 0;
        for (int i = 0; i < nb; i++) { int v = g_bsum[i]; g_bsum[i] = s; s += v; }
    }
}

__global__ void k_scan3() {
    int i = blockIdx.x * blockDim.x + threadIdx.x;
    if (i < NV) {
        int r = g_rowptr[i] + g_bsum[i >> 10];
        g_rowptr[i] = r;
        g_cursor[i] = r;
    }
    if (i == 0) g_rowptr[NV] = ET;
}

__global__ void k_fill_edges(const int* __restrict__ ei) {
    int stride = gridDim.x * blockDim.x;
    for (int i = blockIdx.x * blockDim.x + threadIdx.x; i < EV; i += stride) {
        int s = ei[i], d = ei[EV + i];
        int pos = atomicAdd(&g_cursor[d], 1);
        g_col[pos] = s;
        g_nrm[pos] = g_dinv[s] * g_dinv[d];
    }
}

__global__ void k_fill_self() {
    int i = blockIdx.x * blockDim.x + threadIdx.x;
    if (i < NV) {
        int pos = atomicAdd(&g_cursor[i], 1);
        g_col[pos] = i;
        float di = g_dinv[i];
        g_nrm[pos] = di * di;
    }
}

// ---------------- diffusion ----------------
__global__ void k_init_acc(const float* __restrict__ x, const float* __restrict__ t) {
    int i = blockIdx.x * blockDim.x + threadIdx.x;
    if (i >= NV * 32) return;
    int q = i & 31;
    float4 tv = reinterpret_cast<const float4*>(t)[q];
    float4 xv = reinterpret_cast<const float4*>(x)[i];
    float4 a;
    a.x = expf(-tv.x) * xv.x;
    a.y = expf(-tv.y) * xv.y;
    a.z = expf(-tv.z) * xv.z;
    a.w = expf(-tv.w) * xv.w;
    g_acc[i] = a;
}

__global__ __launch_bounds__(256) void k_hop(const float* __restrict__ x,
                                             const float* __restrict__ t, int k) {
    int w = (blockIdx.x * blockDim.x + threadIdx.x) >> 5;
    int lane = threadIdx.x & 31;
    if (w >= NV) return;
    const float4* hin;
    if (k == 1) hin = reinterpret_cast<const float4*>(x);
    else        hin = (k & 1) ? g_hB : g_hA;
    float4* hout = (k & 1) ? g_hA : g_hB;

    int beg = g_rowptr[w], end = g_rowptr[w + 1];
    float4 s = make_float4(0.f, 0.f, 0.f, 0.f);
    int j = beg;
    for (; j + 1 < end; j += 2) {
        int s0 = g_col[j], s1 = g_col[j + 1];
        float w0 = g_nrm[j], w1 = g_nrm[j + 1];
        float4 v0 = __ldg(&hin[s0 * 32 + lane]);
        float4 v1 = __ldg(&hin[s1 * 32 + lane]);
        s.x = fmaf(w0, v0.x, s.x); s.y = fmaf(w0, v0.y, s.y);
        s.z = fmaf(w0, v0.z, s.z); s.w = fmaf(w0, v0.w, s.w);
        s.x = fmaf(w1, v1.x, s.x); s.y = fmaf(w1, v1.y, s.y);
        s.z = fmaf(w1, v1.z, s.z); s.w = fmaf(w1, v1.w, s.w);
    }
    if (j < end) {
        int s0 = g_col[j];
        float w0 = g_nrm[j];
        float4 v0 = __ldg(&hin[s0 * 32 + lane]);
        s.x = fmaf(w0, v0.x, s.x); s.y = fmaf(w0, v0.y, s.y);
        s.z = fmaf(w0, v0.z, s.z); s.w = fmaf(w0, v0.w, s.w);
    }
    // coef_k = exp(-t) * prod_{i=1..k} (t/i)  (matches reference update order)
    float4 tv = reinterpret_cast<const float4*>(t)[lane];
    float4 cf;
    cf.x = expf(-tv.x); cf.y = expf(-tv.y); cf.z = expf(-tv.z); cf.w = expf(-tv.w);
    for (int i = 1; i <= k; i++) {
        float inv = 1.f / (float)i;
        cf.x *= tv.x * inv; cf.y *= tv.y * inv; cf.z *= tv.z * inv; cf.w *= tv.w * inv;
    }
    hout[w * 32 + lane] = s;
    float4 a = g_acc[w * 32 + lane];
    a.x = fmaf(cf.x, s.x, a.x); a.y = fmaf(cf.y, s.y, a.y);
    a.z = fmaf(cf.z, s.z, a.z); a.w = fmaf(cf.w, s.w, a.w);
    g_acc[w * 32 + lane] = a;
}

// ---------------- GEMM1 [N,128]@[128,64] + attention logits (head == cs) ----------------
__global__ __launch_bounds__(256) void k_gemm1(const float* __restrict__ W1,
                                               const float* __restrict__ as1,
                                               const float* __restrict__ ad1) {
    __shared__ float sW[64 * 64];     // one K-phase of W1 (16 KB)
    __shared__ float sX[32][132];     // 32 node rows, padded
    int tid = threadIdx.x;
    int nb = blockIdx.x * 32;
    for (int i = tid; i < 1024; i += 256) {
        int r = i >> 5, q = i & 31;
        int n = nb + r;
        float4 v = (n < NV) ? g_acc[n * 32 + q] : make_float4(0, 0, 0, 0);
        *reinterpret_cast<float4*>(&sX[r][q * 4]) = v;
    }
    int node = tid >> 3, cs = tid & 7;
    float4 a0 = make_float4(0, 0, 0, 0), a1 = make_float4(0, 0, 0, 0);
    for (int ph = 0; ph < 2; ph++) {
        __syncthreads();
        const float4* W4 = reinterpret_cast<const float4*>(W1) + ph * 1024;
        for (int i = tid; i < 1024; i += 256) reinterpret_cast<float4*>(sW)[i] = W4[i];
        __syncthreads();
        #pragma unroll 8
        for (int kk = 0; kk < 64; kk++) {
            float xv = sX[node][ph * 64 + kk];
            float4 w0 = *reinterpret_cast<const float4*>(&sW[kk * 64 + cs * 8]);
            float4 w1 = *reinterpret_cast<const float4*>(&sW[kk * 64 + cs * 8 + 4]);
            a0.x = fmaf(xv, w0.x, a0.x); a0.y = fmaf(xv, w0.y, a0.y);
            a0.z = fmaf(xv, w0.z, a0.z); a0.w = fmaf(xv, w0.w, a0.w);
            a1.x = fmaf(xv, w1.x, a1.x); a1.y = fmaf(xv, w1.y, a1.y);
            a1.z = fmaf(xv, w1.z, a1.z); a1.w = fmaf(xv, w1.w, a1.w);
        }
    }
    int n = nb + node;
    if (n < NV) {
        g_h1[n * 16 + cs * 2] = a0;
        g_h1[n * 16 + cs * 2 + 1] = a1;
        const float* s8 = as1 + cs * 8;
        const float* d8 = ad1 + cs * 8;
        float ls = a0.x * s8[0] + a0.y * s8[1] + a0.z * s8[2] + a0.w * s8[3]
                 + a1.x * s8[4] + a1.y * s8[5] + a1.z * s8[6] + a1.w * s8[7];
        float ld_ = a0.x * d8[0] + a0.y * d8[1] + a0.z * d8[2] + a0.w * d8[3]
                  + a1.x * d8[4] + a1.y * d8[5] + a1.z * d8[6] + a1.w * d8[7];
        g_als1[n * 8 + cs] = ls;
        g_ald1[n * 8 + cs] = ld_;
    }
}

// ---------------- GAT1: softmax attention + aggregation + bias + ELU ----------------
__global__ __launch_bounds__(256) void k_gat1(const float* __restrict__ b1) {
    int w = (blockIdx.x * blockDim.x + threadIdx.x) >> 5;
    int lane = threadIdx.x & 31;
    if (w >= NV) return;
    int h = lane >> 2, sub = lane & 3;   // lane owns channels h*8 + sub*2 .. +1
    float adn = g_ald1[w * 8 + h];
    int beg = g_rowptr[w], end = g_rowptr[w + 1];

    float mx = -FLT_MAX;
    for (int j = beg + sub; j < end; j += 4) {
        int s = g_col[j];
        float e = g_als1[s * 8 + h] + adn;
        e = (e > 0.f) ? e : 0.2f * e;
        mx = fmaxf(mx, e);
    }
    mx = fmaxf(mx, __shfl_xor_sync(0xffffffffu, mx, 1));
    mx = fmaxf(mx, __shfl_xor_sync(0xffffffffu, mx, 2));

    float den = 0.f, ox = 0.f, oy = 0.f;
    const float* h1f = reinterpret_cast<const float*>(g_h1);
    for (int j = beg; j < end; j++) {
        int s = g_col[j];
        float e = g_als1[s * 8 + h] + adn;
        e = (e > 0.f) ? e : 0.2f * e;
        float ex = expf(e - mx);
        den += ex;
        float2 hv = *reinterpret_cast<const float2*>(&h1f[s * 64 + h * 8 + sub * 2]);
        ox = fmaf(ex, hv.x, ox);
        oy = fmaf(ex, hv.y, oy);
    }
    float inv = 1.f / fmaxf(den, 1e-16f);
    int c = h * 8 + sub * 2;
    float v0 = ox * inv + b1[c];
    float v1 = oy * inv + b1[c + 1];
    v0 = (v0 > 0.f) ? v0 : expm1f(v0);
    v1 = (v1 > 0.f) ? v1 : expm1f(v1);
    float* act = reinterpret_cast<float*>(g_act1);
    act[w * 64 + c] = v0;
    act[w * 64 + c + 1] = v1;
}

// ---------------- GEMM2 [N,64]@[64,40] + logits ----------------
__global__ __launch_bounds__(256) void k_gemm2(const float* __restrict__ W2,
                                               const float* __restrict__ as2,
                                               const float* __restrict__ ad2) {
    __shared__ float sW[64 * 40];
    __shared__ float sX[32][68];
    int tid = threadIdx.x;
    int nb = blockIdx.x * 32;
    for (int i = tid; i < 2560; i += 256) sW[i] = W2[i];
    for (int i = tid; i < 512; i += 256) {
        int r = i >> 4, q = i & 15;
        int n = nb + r;
        float4 v = (n < NV) ? g_act1[n * 16 + q] : make_float4(0, 0, 0, 0);
        *reinterpret_cast<float4*>(&sX[r][q * 4]) = v;
    }
    __syncthreads();
    int node = tid >> 3, cs = tid & 7;  // thread owns channels cs*5 .. cs*5+4
    float a[5] = {0, 0, 0, 0, 0};
    #pragma unroll 4
    for (int kk = 0; kk < 64; kk++) {
        float xv = sX[node][kk];
        #pragma unroll
        for (int i = 0; i < 5; i++) a[i] = fmaf(xv, sW[kk * 40 + cs * 5 + i], a[i]);
    }
    int n = nb + node;
    float ps = 0.f, pd = 0.f;
    #pragma unroll
    for (int i = 0; i < 5; i++) { ps += a[i] * as2[cs * 5 + i]; pd += a[i] * ad2[cs * 5 + i]; }
    ps += __shfl_xor_sync(0xffffffffu, ps, 1);
    ps += __shfl_xor_sync(0xffffffffu, ps, 2);
    ps += __shfl_xor_sync(0xffffffffu, ps, 4);
    pd += __shfl_xor_sync(0xffffffffu, pd, 1);
    pd += __shfl_xor_sync(0xffffffffu, pd, 2);
    pd += __shfl_xor_sync(0xffffffffu, pd, 4);
    if (n < NV) {
        #pragma unroll
        for (int i = 0; i < 5; i++) g_h2[n * 40 + cs * 5 + i] = a[i];
        if (cs == 0) { g_als2[n] = ps; g_ald2[n] = pd; }
    }
}

// ---------------- GAT2 + bias + log_softmax -> out ----------------
__global__ __launch_bounds__(256) void k_gat2(const float* __restrict__ b2,
                                              float* __restrict__ out) {
    int w = (blockIdx.x * blockDim.x + threadIdx.x) >> 5;
    int lane = threadIdx.x & 31;
    if (w >= NV) return;
    float adn = g_ald2[w];
    int beg = g_rowptr[w], end = g_rowptr[w + 1];

    float mx = -FLT_MAX;
    for (int j = beg + lane; j < end; j += 32) {
        float e = g_als2[g_col[j]] + adn;
        e = (e > 0.f) ? e : 0.2f * e;
        mx = fmaxf(mx, e);
    }
    for (int o = 16; o > 0; o >>= 1) mx = fmaxf(mx, __shfl_xor_sync(0xffffffffu, mx, o));

    float den = 0.f, a0 = 0.f, a1 = 0.f;
    for (int j = beg; j < end; j++) {
        int s = g_col[j];
        float e = g_als2[s] + adn;
        e = (e > 0.f) ? e : 0.2f * e;
        float ex = expf(e - mx);
        den += ex;
        a0 = fmaf(ex, g_h2[s * 40 + lane], a0);
        if (lane < 8) a1 = fmaf(ex, g_h2[s * 40 + 32 + lane], a1);
    }
    float inv = 1.f / fmaxf(den, 1e-16f);
    float v0 = a0 * inv + b2[lane];
    float v1 = (lane < 8) ? (a1 * inv + b2[32 + lane]) : -FLT_MAX;

    float m = fmaxf(v0, v1);
    for (int o = 16; o > 0; o >>= 1) m = fmaxf(m, __shfl_xor_sync(0xffffffffu, m, o));
    float se = expf(v0 - m) + ((lane < 8) ? expf(v1 - m) : 0.f);
    for (int o = 16; o > 0; o >>= 1) se += __shfl_xor_sync(0xffffffffu, se, o);
    float lse = logf(se);
    out[w * 40 + lane] = v0 - m - lse;
    if (lane < 8) out[w * 40 + 32 + lane] = v1 - m - lse;
}

// ---------------- launch ----------------
extern "C" void kernel_launch(void* const* d_in, const int* in_sizes, int n_in,
                              void* d_out, int out_size) {
    const float* x   = (const float*)d_in[0];
    const int*   ei  = (const int*)d_in[1];
    const float* t   = (const float*)d_in[2];
    const float* W1  = (const float*)d_in[3];
    const float* as1 = (const float*)d_in[4];
    const float* ad1 = (const float*)d_in[5];
    const float* b1  = (const float*)d_in[6];
    const float* W2  = (const float*)d_in[7];
    const float* as2 = (const float*)d_in[8];
    const float* ad2 = (const float*)d_in[9];
    const float* b2  = (const float*)d_in[10];
    float* out = (float*)d_out;

    const int NB  = (NV + 255) / 256;          // node-parallel blocks
    const int NWB = (NV * 32 + 255) / 256;     // warp-per-node blocks (12500)
    const int SB  = (NV + 1023) / 1024;        // scan blocks (98)

    // CSR build
    k_zero_deg<<<NB, 256>>>();
    k_count<<<2048, 256>>>(ei);
    k_finish_deg<<<NB, 256>>>();
    k_scan1<<<SB, 1024>>>();
    k_scan2<<<1, 32>>>(SB);
    k_scan3<<<NB, 256>>>();
    k_fill_edges<<<2048, 256>>>(ei);
    k_fill_self<<<NB, 256>>>();

    // diffusion: acc = exp(-t)*x + sum_k coef_k * A^k x
    k_init_acc<<<NWB, 256>>>(x, t);
    for (int k = 1; k <= 10; k++)
        k_hop<<<NWB, 256>>>(x, t, k);

    // GAT layer 1
    k_gemm1<<<(NV + 31) / 32, 256>>>(W1, as1, ad1);
    k_gat1<<<NWB, 256>>>(b1);

    // GAT layer 2 + log_softmax
    k_gemm2<<<(NV + 31) / 32, 256>>>(W2, as2, ad2);
    k_gat2<<<NWB, 256>>>(b2, out);
}

// round 2
// speedup vs baseline: 1.1591x; 1.1591x over previous
#include <cuda_runtime.h>
#include <cuda_fp16.h>
#include <math.h>
#include <float.h>

#define NV 100000
#define EV 1600000
#define ET 1700000   // EV + NV self loops

// ---------------- scratch (static device globals; no allocation) ----------------
__device__ int    g_deg[NV];
__device__ float  g_dinv[NV];
__device__ int    g_rowptr[NV + 1];
__device__ int    g_cursor[NV];
__device__ int    g_bsum[128];
__device__ int    g_col[ET];
__device__ float  g_nrm[ET];
__device__ uint2  g_hA[NV * 32];    // [N,128] half, ping (8B = 4 channels/lane)
__device__ uint2  g_hB[NV * 32];    // [N,128] half, pong
__device__ float4 g_acc[NV * 32];   // diffusion accumulator [N,128] fp32
__device__ __half2 g_h1h[NV * 32];  // [N,64] half
__device__ float  g_als1[NV * 8];
__device__ float  g_ald1[NV * 8];
__device__ float4 g_act1[NV * 16];  // [N,64] after ELU (fp32)
__device__ float  g_h2[NV * 40];
__device__ float  g_als2[NV];
__device__ float  g_ald2[NV];

// ---------------- CSR construction ----------------
__global__ void k_zero_deg() {
    int i = blockIdx.x * blockDim.x + threadIdx.x;
    if (i < NV) g_deg[i] = 0;
}

__global__ void k_count(const int* __restrict__ ei) {
    int stride = gridDim.x * blockDim.x;
    for (int i = blockIdx.x * blockDim.x + threadIdx.x; i < EV; i += stride)
        atomicAdd(&g_deg[ei[EV + i]], 1);
}

__global__ void k_finish_deg() {
    int i = blockIdx.x * blockDim.x + threadIdx.x;
    if (i < NV) {
        int d = g_deg[i] + 1;  // + self loop
        g_deg[i] = d;
        g_dinv[i] = rsqrtf((float)d);
    }
}

__global__ __launch_bounds__(1024) void k_scan1() {
    __shared__ int sh[1024];
    int i = blockIdx.x * 1024 + threadIdx.x;
    int v = (i < NV) ? g_deg[i] : 0;
    sh[threadIdx.x] = v;
    __syncthreads();
    for (int off = 1; off < 1024; off <<= 1) {
        int tv = (threadIdx.x >= off) ? sh[threadIdx.x - off] : 0;
        __syncthreads();
        sh[threadIdx.x] += tv;
        __syncthreads();
    }
    if (i < NV) g_rowptr[i] = sh[threadIdx.x] - v;   // exclusive, block-local
    if (threadIdx.x == 1023) g_bsum[blockIdx.x] = sh[1023];
}

__global__ void k_scan2(int nb) {
    if (threadIdx.x == 0) {
        int s = 0;
        for (int i = 0; i < nb; i++) { int v = g_bsum[i]; g_bsum[i] = s; s += v; }
    }
}

__global__ void k_scan3() {
    int i = blockIdx.x * blockDim.x + threadIdx.x;
    if (i < NV) {
        int r = g_rowptr[i] + g_bsum[i >> 10];
        g_rowptr[i] = r;
        g_cursor[i] = r;
    }
    if (i == 0) g_rowptr[NV] = ET;
}

__global__ void k_fill_edges(const int* __restrict__ ei) {
    int stride = gridDim.x * blockDim.x;
    for (int i = blockIdx.x * blockDim.x + threadIdx.x; i < EV; i += stride) {
        int s = ei[i], d = ei[EV + i];
        int pos = atomicAdd(&g_cursor[d], 1);
        g_col[pos] = s;
        g_nrm[pos] = g_dinv[s] * g_dinv[d];
    }
}

__global__ void k_fill_self() {
    int i = blockIdx.x * blockDim.x + threadIdx.x;
    if (i < NV) {
        int pos = atomicAdd(&g_cursor[i], 1);
        g_col[pos] = i;
        float di = g_dinv[i];
        g_nrm[pos] = di * di;
    }
}

// ---------------- diffusion ----------------
__global__ void k_init_acc(const float* __restrict__ x, const float* __restrict__ t) {
    int i = blockIdx.x * blockDim.x + threadIdx.x;
    if (i >= NV * 32) return;
    int q = i & 31;
    float4 tv = reinterpret_cast<const float4*>(t)[q];
    float4 xv = reinterpret_cast<const float4*>(x)[i];
    float4 a;
    a.x = expf(-tv.x) * xv.x;
    a.y = expf(-tv.y) * xv.y;
    a.z = expf(-tv.z) * xv.z;
    a.w = expf(-tv.w) * xv.w;
    g_acc[i] = a;
    __half2 p0 = __floats2half2_rn(xv.x, xv.y);
    __half2 p1 = __floats2half2_rn(xv.z, xv.w);
    uint2 o;
    o.x = *reinterpret_cast<unsigned int*>(&p0);
    o.y = *reinterpret_cast<unsigned int*>(&p1);
    g_hA[i] = o;   // half copy of x, read by hop k=1
}

__global__ __launch_bounds__(256) void k_hop(const float* __restrict__ t, int k) {
    int w = (blockIdx.x * blockDim.x + threadIdx.x) >> 5;
    int lane = threadIdx.x & 31;
    if (w >= NV) return;
    const uint2* __restrict__ hin = (k & 1) ? g_hA : g_hB;
    uint2* hout = (k & 1) ? g_hB : g_hA;

    int beg = g_rowptr[w], end = g_rowptr[w + 1];
    float sx = 0.f, sy = 0.f, sz = 0.f, sw = 0.f;
    int j = beg;
    for (; j + 1 < end; j += 2) {
        int s0 = g_col[j], s1 = g_col[j + 1];
        float w0 = g_nrm[j], w1 = g_nrm[j + 1];
        uint2 u0 = __ldg(&hin[s0 * 32 + lane]);
        uint2 u1 = __ldg(&hin[s1 * 32 + lane]);
        float2 a0 = __half22float2(*reinterpret_cast<__half2*>(&u0.x));
        float2 b0 = __half22float2(*reinterpret_cast<__half2*>(&u0.y));
        float2 a1 = __half22float2(*reinterpret_cast<__half2*>(&u1.x));
        float2 b1 = __half22float2(*reinterpret_cast<__half2*>(&u1.y));
        sx = fmaf(w0, a0.x, sx); sy = fmaf(w0, a0.y, sy);
        sz = fmaf(w0, b0.x, sz); sw = fmaf(w0, b0.y, sw);
        sx = fmaf(w1, a1.x, sx); sy = fmaf(w1, a1.y, sy);
        sz = fmaf(w1, b1.x, sz); sw = fmaf(w1, b1.y, sw);
    }
    if (j < end) {
        int s0 = g_col[j];
        float w0 = g_nrm[j];
        uint2 u0 = __ldg(&hin[s0 * 32 + lane]);
        float2 a0 = __half22float2(*reinterpret_cast<__half2*>(&u0.x));
        float2 b0 = __half22float2(*reinterpret_cast<__half2*>(&u0.y));
        sx = fmaf(w0, a0.x, sx); sy = fmaf(w0, a0.y, sy);
        sz = fmaf(w0, b0.x, sz); sw = fmaf(w0, b0.y, sw);
    }
    // coef_k = exp(-t) * prod_{i=1..k} (t/i)  (matches reference update order)
    float4 tv = reinterpret_cast<const float4*>(t)[lane];
    float4 cf;
    cf.x = expf(-tv.x); cf.y = expf(-tv.y); cf.z = expf(-tv.z); cf.w = expf(-tv.w);
    for (int i = 1; i <= k; i++) {
        float inv = 1.f / (float)i;
        cf.x *= tv.x * inv; cf.y *= tv.y * inv; cf.z *= tv.z * inv; cf.w *= tv.w * inv;
    }
    if (k < 10) {   // last hop's h is never read again
        __half2 p0 = __floats2half2_rn(sx, sy);
        __half2 p1 = __floats2half2_rn(sz, sw);
        uint2 o;
        o.x = *reinterpret_cast<unsigned int*>(&p0);
        o.y = *reinterpret_cast<unsigned int*>(&p1);
        hout[w * 32 + lane] = o;
    }
    float4 a = g_acc[w * 32 + lane];
    a.x = fmaf(cf.x, sx, a.x); a.y = fmaf(cf.y, sy, a.y);
    a.z = fmaf(cf.z, sz, a.z); a.w = fmaf(cf.w, sw, a.w);
    g_acc[w * 32 + lane] = a;
}

// ---------------- GEMM1 [N,128]@[128,64] + attention logits (head == cs) ----------------
__global__ __launch_bounds__(256) void k_gemm1(const float* __restrict__ W1,
                                               const float* __restrict__ as1,
                                               const float* __restrict__ ad1) {
    __shared__ float sW[64 * 64];     // one K-phase of W1 (16 KB)
    __shared__ float sX[32][132];     // 32 node rows, padded
    int tid = threadIdx.x;
    int nb = blockIdx.x * 32;
    for (int i = tid; i < 1024; i += 256) {
        int r = i >> 5, q = i & 31;
        int n = nb + r;
        float4 v = (n < NV) ? g_acc[n * 32 + q] : make_float4(0, 0, 0, 0);
        *reinterpret_cast<float4*>(&sX[r][q * 4]) = v;
    }
    int node = tid >> 3, cs = tid & 7;
    float4 a0 = make_float4(0, 0, 0, 0), a1 = make_float4(0, 0, 0, 0);
    for (int ph = 0; ph < 2; ph++) {
        __syncthreads();
        const float4* W4 = reinterpret_cast<const float4*>(W1) + ph * 1024;
        for (int i = tid; i < 1024; i += 256) reinterpret_cast<float4*>(sW)[i] = W4[i];
        __syncthreads();
        #pragma unroll 8
        for (int kk = 0; kk < 64; kk++) {
            float xv = sX[node][ph * 64 + kk];
            float4 w0 = *reinterpret_cast<const float4*>(&sW[kk * 64 + cs * 8]);
            float4 w1 = *reinterpret_cast<const float4*>(&sW[kk * 64 + cs * 8 + 4]);
            a0.x = fmaf(xv, w0.x, a0.x); a0.y = fmaf(xv, w0.y, a0.y);
            a0.z = fmaf(xv, w0.z, a0.z); a0.w = fmaf(xv, w0.w, a0.w);
            a1.x = fmaf(xv, w1.x, a1.x); a1.y = fmaf(xv, w1.y, a1.y);
            a1.z = fmaf(xv, w1.z, a1.z); a1.w = fmaf(xv, w1.w, a1.w);
        }
    }
    int n = nb + node;
    if (n < NV) {
        __half2* p = &g_h1h[n * 32 + cs * 4];
        p[0] = __floats2half2_rn(a0.x, a0.y);
        p[1] = __floats2half2_rn(a0.z, a0.w);
        p[2] = __floats2half2_rn(a1.x, a1.y);
        p[3] = __floats2half2_rn(a1.z, a1.w);
        const float* s8 = as1 + cs * 8;
        const float* d8 = ad1 + cs * 8;
        float ls = a0.x * s8[0] + a0.y * s8[1] + a0.z * s8[2] + a0.w * s8[3]
                 + a1.x * s8[4] + a1.y * s8[5] + a1.z * s8[6] + a1.w * s8[7];
        float ld_ = a0.x * d8[0] + a0.y * d8[1] + a0.z * d8[2] + a0.w * d8[3]
                  + a1.x * d8[4] + a1.y * d8[5] + a1.z * d8[6] + a1.w * d8[7];
        g_als1[n * 8 + cs] = ls;
        g_ald1[n * 8 + cs] = ld_;
    }
}

// ---------------- GAT1: softmax attention + aggregation + bias + ELU ----------------
__global__ __launch_bounds__(256) void k_gat1(const float* __restrict__ b1) {
    int w = (blockIdx.x * blockDim.x + threadIdx.x) >> 5;
    int lane = threadIdx.x & 31;
    if (w >= NV) return;
    int h = lane >> 2, sub = lane & 3;   // lane owns channels h*8 + sub*2 .. +1
    float adn = g_ald1[w * 8 + h];
    int beg = g_rowptr[w], end = g_rowptr[w + 1];

    float mx = -FLT_MAX;
    for (int j = beg + sub; j < end; j += 4) {
        int s = g_col[j];
        float e = g_als1[s * 8 + h] + adn;
        e = (e > 0.f) ? e : 0.2f * e;
        mx = fmaxf(mx, e);
    }
    mx = fmaxf(mx, __shfl_xor_sync(0xffffffffu, mx, 1));
    mx = fmaxf(mx, __shfl_xor_sync(0xffffffffu, mx, 2));

    float den = 0.f, ox = 0.f, oy = 0.f;
    for (int j = beg; j < end; j++) {
        int s = g_col[j];
        float e = g_als1[s * 8 + h] + adn;
        e = (e > 0.f) ? e : 0.2f * e;
        float ex = expf(e - mx);
        den += ex;
        float2 hv = __half22float2(__ldg(&g_h1h[s * 32 + h * 4 + sub]));
        ox = fmaf(ex, hv.x, ox);
        oy = fmaf(ex, hv.y, oy);
    }
    float inv = 1.f / fmaxf(den, 1e-16f);
    int c = h * 8 + sub * 2;
    float v0 = ox * inv + b1[c];
    float v1 = oy * inv + b1[c + 1];
    v0 = (v0 > 0.f) ? v0 : expm1f(v0);
    v1 = (v1 > 0.f) ? v1 : expm1f(v1);
    float* act = reinterpret_cast<float*>(g_act1);
    act[w * 64 + c] = v0;
    act[w * 64 + c + 1] = v1;
}

// ---------------- GEMM2 [N,64]@[64,40] + logits ----------------
__global__ __launch_bounds__(256) void k_gemm2(const float* __restrict__ W2,
                                               const float* __restrict__ as2,
                                               const float* __restrict__ ad2) {
    __shared__ float sW[64 * 40];
    __shared__ float sX[32][68];
    int tid = threadIdx.x;
    int nb = blockIdx.x * 32;
    for (int i = tid; i < 2560; i += 256) sW[i] = W2[i];
    for (int i = tid; i < 512; i += 256) {
        int r = i >> 4, q = i & 15;
        int n = nb + r;
        float4 v = (n < NV) ? g_act1[n * 16 + q] : make_float4(0, 0, 0, 0);
        *reinterpret_cast<float4*>(&sX[r][q * 4]) = v;
    }
    __syncthreads();
    int node = tid >> 3, cs = tid & 7;  // thread owns channels cs*5 .. cs*5+4
    float a[5] = {0, 0, 0, 0, 0};
    #pragma unroll 4
    for (int kk = 0; kk < 64; kk++) {
        float xv = sX[node][kk];
        #pragma unroll
        for (int i = 0; i < 5; i++) a[i] = fmaf(xv, sW[kk * 40 + cs * 5 + i], a[i]);
    }
    int n = nb + node;
    float ps = 0.f, pd = 0.f;
    #pragma unroll
    for (int i = 0; i < 5; i++) { ps += a[i] * as2[cs * 5 + i]; pd += a[i] * ad2[cs * 5 + i]; }
    ps += __shfl_xor_sync(0xffffffffu, ps, 1);
    ps += __shfl_xor_sync(0xffffffffu, ps, 2);
    ps += __shfl_xor_sync(0xffffffffu, ps, 4);
    pd += __shfl_xor_sync(0xffffffffu, pd, 1);
    pd += __shfl_xor_sync(0xffffffffu, pd, 2);
    pd += __shfl_xor_sync(0xffffffffu, pd, 4);
    if (n < NV) {
        #pragma unroll
        for (int i = 0; i < 5; i++) g_h2[n * 40 + cs * 5 + i] = a[i];
        if (cs == 0) { g_als2[n] = ps; g_ald2[n] = pd; }
    }
}

// ---------------- GAT2 + bias + log_softmax -> out ----------------
__global__ __launch_bounds__(256) void k_gat2(const float* __restrict__ b2,
                                              float* __restrict__ out) {
    int w = (blockIdx.x * blockDim.x + threadIdx.x) >> 5;
    int lane = threadIdx.x & 31;
    if (w >= NV) return;
    float adn = g_ald2[w];
    int beg = g_rowptr[w], end = g_rowptr[w + 1];

    float mx = -FLT_MAX;
    for (int j = beg + lane; j < end; j += 32) {
        float e = g_als2[g_col[j]] + adn;
        e = (e > 0.f) ? e : 0.2f * e;
        mx = fmaxf(mx, e);
    }
    for (int o = 16; o > 0; o >>= 1) mx = fmaxf(mx, __shfl_xor_sync(0xffffffffu, mx, o));

    float den = 0.f, a0 = 0.f, a1 = 0.f;
    for (int j = beg; j < end; j++) {
        int s = g_col[j];
        float e = g_als2[s] + adn;
        e = (e > 0.f) ? e : 0.2f * e;
        float ex = expf(e - mx);
        den += ex;
        a0 = fmaf(ex, g_h2[s * 40 + lane], a0);
        if (lane < 8) a1 = fmaf(ex, g_h2[s * 40 + 32 + lane], a1);
    }
    float inv = 1.f / fmaxf(den, 1e-16f);
    float v0 = a0 * inv + b2[lane];
    float v1 = (lane < 8) ? (a1 * inv + b2[32 + lane]) : -FLT_MAX;

    float m = fmaxf(v0, v1);
    for (int o = 16; o > 0; o >>= 1) m = fmaxf(m, __shfl_xor_sync(0xffffffffu, m, o));
    float se = expf(v0 - m) + ((lane < 8) ? expf(v1 - m) : 0.f);
    for (int o = 16; o > 0; o >>= 1) se += __shfl_xor_sync(0xffffffffu, se, o);
    float lse = logf(se);
    out[w * 40 + lane] = v0 - m - lse;
    if (lane < 8) out[w * 40 + 32 + lane] = v1 - m - lse;
}

// ---------------- launch ----------------
extern "C" void kernel_launch(void* const* d_in, const int* in_sizes, int n_in,
                              void* d_out, int out_size) {
    const float* x   = (const float*)d_in[0];
    const int*   ei  = (const int*)d_in[1];
    const float* t   = (const float*)d_in[2];
    const float* W1  = (const float*)d_in[3];
    const float* as1 = (const float*)d_in[4];
    const float* ad1 = (const float*)d_in[5];
    const float* b1  = (const float*)d_in[6];
    const float* W2  = (const float*)d_in[7];
    const float* as2 = (const float*)d_in[8];
    const float* ad2 = (const float*)d_in[9];
    const float* b2  = (const float*)d_in[10];
    float* out = (float*)d_out;

    const int NB  = (NV + 255) / 256;          // node-parallel blocks
    const int NWB = (NV * 32 + 255) / 256;     // warp-per-node blocks (12500)
    const int SB  = (NV + 1023) / 1024;        // scan blocks (98)

    // CSR build
    k_zero_deg<<<NB, 256>>>();
    k_count<<<2048, 256>>>(ei);
    k_finish_deg<<<NB, 256>>>();
    k_scan1<<<SB, 1024>>>();
    k_scan2<<<1, 32>>>(SB);
    k_scan3<<<NB, 256>>>();
    k_fill_edges<<<2048, 256>>>(ei);
    k_fill_self<<<NB, 256>>>();

    // diffusion: acc = exp(-t)*x + sum_k coef_k * A^k x
    k_init_acc<<<NWB, 256>>>(x, t);
    for (int k = 1; k <= 10; k++)
        k_hop<<<NWB, 256>>>(t, k);

    // GAT layer 1
    k_gemm1<<<(NV + 31) / 32, 256>>>(W1, as1, ad1);
    k_gat1<<<NWB, 256>>>(b1);

    // GAT layer 2 + log_softmax
    k_gemm2<<<(NV + 31) / 32, 256>>>(W2, as2, ad2);
    k_gat2<<<NWB, 256>>>(b2, out);
}

// round 3
// speedup vs baseline: 1.3792x; 1.1898x over previous
#include <cuda_runtime.h>
#include <cuda_fp16.h>
#include <math.h>
#include <float.h>

#define NV 100000
#define EV 1600000
#define ET 1700000   // EV + NV self loops

// ---------------- scratch (static device globals; no allocation) ----------------
__device__ int    g_deg[NV];
__device__ float  g_dinv[NV];
__device__ int    g_rowptr[NV + 1];
__device__ int    g_cursor[NV];
__device__ int    g_bsum[128];
__device__ int    g_col[ET];
__device__ float  g_nrm[ET];
__device__ uint2  g_h[11][NV * 32];   // h_0..h_10, each [N,128] in half (8B = 4 ch/lane)
__device__ __half2 g_h1h[NV * 32];    // [N,64] half (GAT1 features)
__device__ float  g_als1[NV * 8];
__device__ float  g_ald1[NV * 8];
__device__ float4 g_act1[NV * 16];    // [N,64] after ELU (fp32)
__device__ float  g_h2[NV * 40];
__device__ float  g_als2[NV];
__device__ float  g_ald2[NV];

// ---------------- CSR construction ----------------
__global__ void k_zero_deg() {
    int i = blockIdx.x * blockDim.x + threadIdx.x;
    if (i < NV) g_deg[i] = 0;
}

__global__ void k_count(const int* __restrict__ ei) {
    int stride = gridDim.x * blockDim.x;
    for (int i = blockIdx.x * blockDim.x + threadIdx.x; i < EV; i += stride)
        atomicAdd(&g_deg[ei[EV + i]], 1);
}

__global__ void k_finish_deg() {
    int i = blockIdx.x * blockDim.x + threadIdx.x;
    if (i < NV) {
        int d = g_deg[i] + 1;  // + self loop
        g_deg[i] = d;
        g_dinv[i] = rsqrtf((float)d);
    }
}

__global__ __launch_bounds__(1024) void k_scan1() {
    __shared__ int sh[1024];
    int i = blockIdx.x * 1024 + threadIdx.x;
    int v = (i < NV) ? g_deg[i] : 0;
    sh[threadIdx.x] = v;
    __syncthreads();
    for (int off = 1; off < 1024; off <<= 1) {
        int tv = (threadIdx.x >= off) ? sh[threadIdx.x - off] : 0;
        __syncthreads();
        sh[threadIdx.x] += tv;
        __syncthreads();
    }
    if (i < NV) g_rowptr[i] = sh[threadIdx.x] - v;   // exclusive, block-local
    if (threadIdx.x == 1023) g_bsum[blockIdx.x] = sh[1023];
}

__global__ void k_scan2(int nb) {
    if (threadIdx.x == 0) {
        int s = 0;
        for (int i = 0; i < nb; i++) { int v = g_bsum[i]; g_bsum[i] = s; s += v; }
    }
}

__global__ void k_scan3() {
    int i = blockIdx.x * blockDim.x + threadIdx.x;
    if (i < NV) {
        int r = g_rowptr[i] + g_bsum[i >> 10];
        g_rowptr[i] = r;
        g_cursor[i] = r;
    }
    if (i == 0) g_rowptr[NV] = ET;
}

__global__ void k_fill_edges(const int* __restrict__ ei) {
    int stride = gridDim.x * blockDim.x;
    for (int i = blockIdx.x * blockDim.x + threadIdx.x; i < EV; i += stride) {
        int s = ei[i], d = ei[EV + i];
        int pos = atomicAdd(&g_cursor[d], 1);
        g_col[pos] = s;
        g_nrm[pos] = g_dinv[s] * g_dinv[d];
    }
}

__global__ void k_fill_self() {
    int i = blockIdx.x * blockDim.x + threadIdx.x;
    if (i < NV) {
        int pos = atomicAdd(&g_cursor[i], 1);
        g_col[pos] = i;
        float di = g_dinv[i];
        g_nrm[pos] = di * di;
    }
}

// ---------------- diffusion ----------------
__global__ void k_init_h0(const float* __restrict__ x) {
    int i = blockIdx.x * blockDim.x + threadIdx.x;
    if (i >= NV * 32) return;
    float4 xv = reinterpret_cast<const float4*>(x)[i];
    __half2 p0 = __floats2half2_rn(xv.x, xv.y);
    __half2 p1 = __floats2half2_rn(xv.z, xv.w);
    uint2 o;
    o.x = *reinterpret_cast<unsigned int*>(&p0);
    o.y = *reinterpret_cast<unsigned int*>(&p1);
    g_h[0][i] = o;
}

__device__ __forceinline__ void acc_edge(float w0, uint2 u0,
                                         float& sx, float& sy, float& sz, float& sw) {
    float2 a0 = __half22float2(*reinterpret_cast<__half2*>(&u0.x));
    float2 b0 = __half22float2(*reinterpret_cast<__half2*>(&u0.y));
    sx = fmaf(w0, a0.x, sx); sy = fmaf(w0, a0.y, sy);
    sz = fmaf(w0, b0.x, sz); sw = fmaf(w0, b0.y, sw);
}

__global__ __launch_bounds__(256) void k_hop(const uint2* __restrict__ hin,
                                             uint2* __restrict__ hout) {
    int w = (blockIdx.x * blockDim.x + threadIdx.x) >> 5;
    int lane = threadIdx.x & 31;
    if (w >= NV) return;

    int beg = g_rowptr[w], end = g_rowptr[w + 1];
    float sx = 0.f, sy = 0.f, sz = 0.f, sw = 0.f;
    int j = beg;
    for (; j + 3 < end; j += 4) {
        int s0 = g_col[j], s1 = g_col[j + 1], s2 = g_col[j + 2], s3 = g_col[j + 3];
        float w0 = g_nrm[j], w1 = g_nrm[j + 1], w2 = g_nrm[j + 2], w3 = g_nrm[j + 3];
        uint2 u0 = __ldg(&hin[s0 * 32 + lane]);
        uint2 u1 = __ldg(&hin[s1 * 32 + lane]);
        uint2 u2 = __ldg(&hin[s2 * 32 + lane]);
        uint2 u3 = __ldg(&hin[s3 * 32 + lane]);
        acc_edge(w0, u0, sx, sy, sz, sw);
        acc_edge(w1, u1, sx, sy, sz, sw);
        acc_edge(w2, u2, sx, sy, sz, sw);
        acc_edge(w3, u3, sx, sy, sz, sw);
    }
    for (; j < end; j++) {
        int s0 = g_col[j];
        float w0 = g_nrm[j];
        uint2 u0 = __ldg(&hin[s0 * 32 + lane]);
        acc_edge(w0, u0, sx, sy, sz, sw);
    }
    __half2 p0 = __floats2half2_rn(sx, sy);
    __half2 p1 = __floats2half2_rn(sz, sw);
    uint2 o;
    o.x = *reinterpret_cast<unsigned int*>(&p0);
    o.y = *reinterpret_cast<unsigned int*>(&p1);
    hout[w * 32 + lane] = o;
}

// -------- GEMM1 [N,128]@[128,64] + Taylor combine + attention logits --------
__global__ __launch_bounds__(256) void k_gemm1(const float* __restrict__ x,
                                               const float* __restrict__ t,
                                               const float* __restrict__ W1,
                                               const float* __restrict__ as1,
                                               const float* __restrict__ ad1) {
    __shared__ float sW[64 * 64];     // one K-phase of W1 (16 KB)
    __shared__ float sX[32][132];     // 32 combined node rows, padded
    int tid = threadIdx.x;
    int nb = blockIdx.x * 32;

    // stage: sX[r][4q..4q+3] = sum_k c_k(t) * h_k  (k=0 term from fp32 x)
    for (int i = tid; i < 1024; i += 256) {
        int r = i >> 5, q = i & 31;
        int n = nb + r;
        float4 a = make_float4(0, 0, 0, 0);
        if (n < NV) {
            float4 tv = reinterpret_cast<const float4*>(t)[q];
            float4 cf;
            cf.x = expf(-tv.x); cf.y = expf(-tv.y);
            cf.z = expf(-tv.z); cf.w = expf(-tv.w);
            float4 xv = reinterpret_cast<const float4*>(x)[n * 32 + q];
            a.x = cf.x * xv.x; a.y = cf.y * xv.y;
            a.z = cf.z * xv.z; a.w = cf.w * xv.w;
            #pragma unroll
            for (int k = 1; k <= 10; k++) {
                float inv = 1.f / (float)k;
                cf.x *= tv.x * inv; cf.y *= tv.y * inv;
                cf.z *= tv.z * inv; cf.w *= tv.w * inv;
                uint2 u = __ldg(&g_h[k][n * 32 + q]);
                float2 lo = __half22float2(*reinterpret_cast<__half2*>(&u.x));
                float2 hi = __half22float2(*reinterpret_cast<__half2*>(&u.y));
                a.x = fmaf(cf.x, lo.x, a.x); a.y = fmaf(cf.y, lo.y, a.y);
                a.z = fmaf(cf.z, hi.x, a.z); a.w = fmaf(cf.w, hi.y, a.w);
            }
        }
        *reinterpret_cast<float4*>(&sX[r][q * 4]) = a;
    }

    int node = tid >> 3, cs = tid & 7;
    float4 a0 = make_float4(0, 0, 0, 0), a1 = make_float4(0, 0, 0, 0);
    for (int ph = 0; ph < 2; ph++) {
        __syncthreads();
        const float4* W4 = reinterpret_cast<const float4*>(W1) + ph * 1024;
        for (int i = tid; i < 1024; i += 256) reinterpret_cast<float4*>(sW)[i] = W4[i];
        __syncthreads();
        #pragma unroll 8
        for (int kk = 0; kk < 64; kk++) {
            float xv = sX[node][ph * 64 + kk];
            float4 w0 = *reinterpret_cast<const float4*>(&sW[kk * 64 + cs * 8]);
            float4 w1 = *reinterpret_cast<const float4*>(&sW[kk * 64 + cs * 8 + 4]);
            a0.x = fmaf(xv, w0.x, a0.x); a0.y = fmaf(xv, w0.y, a0.y);
            a0.z = fmaf(xv, w0.z, a0.z); a0.w = fmaf(xv, w0.w, a0.w);
            a1.x = fmaf(xv, w1.x, a1.x); a1.y = fmaf(xv, w1.y, a1.y);
            a1.z = fmaf(xv, w1.z, a1.z); a1.w = fmaf(xv, w1.w, a1.w);
        }
    }
    int n = nb + node;
    if (n < NV) {
        __half2* p = &g_h1h[n * 32 + cs * 4];
        p[0] = __floats2half2_rn(a0.x, a0.y);
        p[1] = __floats2half2_rn(a0.z, a0.w);
        p[2] = __floats2half2_rn(a1.x, a1.y);
        p[3] = __floats2half2_rn(a1.z, a1.w);
        const float* s8 = as1 + cs * 8;
        const float* d8 = ad1 + cs * 8;
        float ls = a0.x * s8[0] + a0.y * s8[1] + a0.z * s8[2] + a0.w * s8[3]
                 + a1.x * s8[4] + a1.y * s8[5] + a1.z * s8[6] + a1.w * s8[7];
        float ld_ = a0.x * d8[0] + a0.y * d8[1] + a0.z * d8[2] + a0.w * d8[3]
                  + a1.x * d8[4] + a1.y * d8[5] + a1.z * d8[6] + a1.w * d8[7];
        g_als1[n * 8 + cs] = ls;
        g_ald1[n * 8 + cs] = ld_;
    }
}

// ---------------- GAT1: softmax attention + aggregation + bias + ELU ----------------
__global__ __launch_bounds__(256) void k_gat1(const float* __restrict__ b1) {
    int w = (blockIdx.x * blockDim.x + threadIdx.x) >> 5;
    int lane = threadIdx.x & 31;
    if (w >= NV) return;
    int h = lane >> 2, sub = lane & 3;   // lane owns channels h*8 + sub*2 .. +1
    float adn = g_ald1[w * 8 + h];
    int beg = g_rowptr[w], end = g_rowptr[w + 1];

    float mx = -FLT_MAX;
    for (int j = beg + sub; j < end; j += 4) {
        int s = g_col[j];
        float e = g_als1[s * 8 + h] + adn;
        e = (e > 0.f) ? e : 0.2f * e;
        mx = fmaxf(mx, e);
    }
    mx = fmaxf(mx, __shfl_xor_sync(0xffffffffu, mx, 1));
    mx = fmaxf(mx, __shfl_xor_sync(0xffffffffu, mx, 2));

    float den = 0.f, ox = 0.f, oy = 0.f;
    for (int j = beg; j < end; j++) {
        int s = g_col[j];
        float e = g_als1[s * 8 + h] + adn;
        e = (e > 0.f) ? e : 0.2f * e;
        float ex = expf(e - mx);
        den += ex;
        float2 hv = __half22float2(__ldg(&g_h1h[s * 32 + h * 4 + sub]));
        ox = fmaf(ex, hv.x, ox);
        oy = fmaf(ex, hv.y, oy);
    }
    float inv = 1.f / fmaxf(den, 1e-16f);
    int c = h * 8 + sub * 2;
    float v0 = ox * inv + b1[c];
    float v1 = oy * inv + b1[c + 1];
    v0 = (v0 > 0.f) ? v0 : expm1f(v0);
    v1 = (v1 > 0.f) ? v1 : expm1f(v1);
    float* act = reinterpret_cast<float*>(g_act1);
    act[w * 64 + c] = v0;
    act[w * 64 + c + 1] = v1;
}

// ---------------- GEMM2 [N,64]@[64,40] + logits ----------------
__global__ __launch_bounds__(256) void k_gemm2(const float* __restrict__ W2,
                                               const float* __restrict__ as2,
                                               const float* __restrict__ ad2) {
    __shared__ float sW[64 * 40];
    __shared__ float sX[32][68];
    int tid = threadIdx.x;
    int nb = blockIdx.x * 32;
    for (int i = tid; i < 2560; i += 256) sW[i] = W2[i];
    for (int i = tid; i < 512; i += 256) {
        int r = i >> 4, q = i & 15;
        int n = nb + r;
        float4 v = (n < NV) ? g_act1[n * 16 + q] : make_float4(0, 0, 0, 0);
        *reinterpret_cast<float4*>(&sX[r][q * 4]) = v;
    }
    __syncthreads();
    int node = tid >> 3, cs = tid & 7;  // thread owns channels cs*5 .. cs*5+4
    float a[5] = {0, 0, 0, 0, 0};
    #pragma unroll 4
    for (int kk = 0; kk < 64; kk++) {
        float xv = sX[node][kk];
        #pragma unroll
        for (int i = 0; i < 5; i++) a[i] = fmaf(xv, sW[kk * 40 + cs * 5 + i], a[i]);
    }
    int n = nb + node;
    float ps = 0.f, pd = 0.f;
    #pragma unroll
    for (int i = 0; i < 5; i++) { ps += a[i] * as2[cs * 5 + i]; pd += a[i] * ad2[cs * 5 + i]; }
    ps += __shfl_xor_sync(0xffffffffu, ps, 1);
    ps += __shfl_xor_sync(0xffffffffu, ps, 2);
    ps += __shfl_xor_sync(0xffffffffu, ps, 4);
    pd += __shfl_xor_sync(0xffffffffu, pd, 1);
    pd += __shfl_xor_sync(0xffffffffu, pd, 2);
    pd += __shfl_xor_sync(0xffffffffu, pd, 4);
    if (n < NV) {
        #pragma unroll
        for (int i = 0; i < 5; i++) g_h2[n * 40 + cs * 5 + i] = a[i];
        if (cs == 0) { g_als2[n] = ps; g_ald2[n] = pd; }
    }
}

// ---------------- GAT2 + bias + log_softmax -> out ----------------
__global__ __launch_bounds__(256) void k_gat2(const float* __restrict__ b2,
                                              float* __restrict__ out) {
    int w = (blockIdx.x * blockDim.x + threadIdx.x) >> 5;
    int lane = threadIdx.x & 31;
    if (w >= NV) return;
    float adn = g_ald2[w];
    int beg = g_rowptr[w], end = g_rowptr[w + 1];

    float mx = -FLT_MAX;
    for (int j = beg + lane; j < end; j += 32) {
        float e = g_als2[g_col[j]] + adn;
        e = (e > 0.f) ? e : 0.2f * e;
        mx = fmaxf(mx, e);
    }
    for (int o = 16; o > 0; o >>= 1) mx = fmaxf(mx, __shfl_xor_sync(0xffffffffu, mx, o));

    float den = 0.f, a0 = 0.f, a1 = 0.f;
    for (int j = beg; j < end; j++) {
        int s = g_col[j];
        float e = g_als2[s] + adn;
        e = (e > 0.f) ? e : 0.2f * e;
        float ex = expf(e - mx);
        den += ex;
        a0 = fmaf(ex, g_h2[s * 40 + lane], a0);
        if (lane < 8) a1 = fmaf(ex, g_h2[s * 40 + 32 + lane], a1);
    }
    float inv = 1.f / fmaxf(den, 1e-16f);
    float v0 = a0 * inv + b2[lane];
    float v1 = (lane < 8) ? (a1 * inv + b2[32 + lane]) : -FLT_MAX;

    float m = fmaxf(v0, v1);
    for (int o = 16; o > 0; o >>= 1) m = fmaxf(m, __shfl_xor_sync(0xffffffffu, m, o));
    float se = expf(v0 - m) + ((lane < 8) ? expf(v1 - m) : 0.f);
    for (int o = 16; o > 0; o >>= 1) se += __shfl_xor_sync(0xffffffffu, se, o);
    float lse = logf(se);
    out[w * 40 + lane] = v0 - m - lse;
    if (lane < 8) out[w * 40 + 32 + lane] = v1 - m - lse;
}

// ---------------- launch ----------------
extern "C" void kernel_launch(void* const* d_in, const int* in_sizes, int n_in,
                              void* d_out, int out_size) {
    const float* x   = (const float*)d_in[0];
    const int*   ei  = (const int*)d_in[1];
    const float* t   = (const float*)d_in[2];
    const float* W1  = (const float*)d_in[3];
    const float* as1 = (const float*)d_in[4];
    const float* ad1 = (const float*)d_in[5];
    const float* b1  = (const float*)d_in[6];
    const float* W2  = (const float*)d_in[7];
    const float* as2 = (const float*)d_in[8];
    const float* ad2 = (const float*)d_in[9];
    const float* b2  = (const float*)d_in[10];
    float* out = (float*)d_out;

    const int NB  = (NV + 255) / 256;          // node-parallel blocks
    const int NWB = (NV * 32 + 255) / 256;     // warp-per-node blocks (12500)
    const int SB  = (NV + 1023) / 1024;        // scan blocks (98)

    // CSR build
    k_zero_deg<<<NB, 256>>>();
    k_count<<<2048, 256>>>(ei);
    k_finish_deg<<<NB, 256>>>();
    k_scan1<<<SB, 1024>>>();
    k_scan2<<<1, 32>>>(SB);
    k_scan3<<<NB, 256>>>();
    k_fill_edges<<<2048, 256>>>(ei);
    k_fill_self<<<NB, 256>>>();

    // diffusion hops: h_k = A_hat h_{k-1}, all in fp16
    k_init_h0<<<NWB, 256>>>(x);
    uint2* hbase;
    cudaGetSymbolAddress((void**)&hbase, g_h);
    for (int k = 1; k <= 10; k++)
        k_hop<<<NWB, 256>>>(hbase + (size_t)(k - 1) * NV * 32,
                            hbase + (size_t)k * NV * 32);

    // GAT layer 1 (Taylor combine fused into staging)
    k_gemm1<<<(NV + 31) / 32, 256>>>(x, t, W1, as1, ad1);
    k_gat1<<<NWB, 256>>>(b1);

    // GAT layer 2 + log_softmax
    k_gemm2<<<(NV + 31) / 32, 256>>>(W2, as2, ad2);
    k_gat2<<<NWB, 256>>>(b2, out);
}

// round 4
// speedup vs baseline: 1.4729x; 1.0679x over previous
#include <cuda_runtime.h>
#include <cuda_fp16.h>
#include <cuda_fp8.h>
#include <math.h>
#include <float.h>

#define NV 100000
#define EV 1600000
#define ET 1700000   // EV + NV self loops

// ---------------- scratch (static device globals; no allocation) ----------------
__device__ int    g_deg[NV];
__device__ float  g_dinv[NV];
__device__ int    g_rowptr[NV + 1];
__device__ int    g_cursor[NV];
__device__ int    g_bsum[128];
__device__ int2   g_edge[ET];          // (src, norm-as-int) packed
__device__ unsigned int g_h[11][NV * 32];  // h_0..h_10, [N,128] fp8 e4m3 (4B = 4 ch/lane)
__device__ __half2 g_h1h[NV * 32];     // [N,64] half (GAT1 features)
__device__ float  g_als1[NV * 8];
__device__ float  g_ald1[NV * 8];
__device__ float4 g_act1[NV * 16];     // [N,64] after ELU (fp32)
__device__ float  g_h2[NV * 40];
__device__ float  g_als2[NV];
__device__ float  g_ald2[NV];

// ---------------- fp8 helpers ----------------
__device__ __forceinline__ unsigned int pack_fp8x4(float a, float b, float c, float d) {
    __nv_fp8x2_storage_t lo = __nv_cvt_float2_to_fp8x2(make_float2(a, b), __NV_SATFINITE, __NV_E4M3);
    __nv_fp8x2_storage_t hi = __nv_cvt_float2_to_fp8x2(make_float2(c, d), __NV_SATFINITE, __NV_E4M3);
    return (unsigned int)lo | ((unsigned int)hi << 16);
}
__device__ __forceinline__ void unpack_fp8x4(unsigned int u, float2& lo, float2& hi) {
    __half2_raw rl = __nv_cvt_fp8x2_to_halfraw2((__nv_fp8x2_storage_t)(u & 0xffffu), __NV_E4M3);
    __half2_raw rh = __nv_cvt_fp8x2_to_halfraw2((__nv_fp8x2_storage_t)(u >> 16), __NV_E4M3);
    lo = __half22float2(*reinterpret_cast<__half2*>(&rl));
    hi = __half22float2(*reinterpret_cast<__half2*>(&rh));
}

// ---------------- CSR construction ----------------
__global__ void k_zero_deg() {
    int i = blockIdx.x * blockDim.x + threadIdx.x;
    if (i < NV) g_deg[i] = 0;
}

__global__ void k_count(const int* __restrict__ ei) {
    int stride = gridDim.x * blockDim.x;
    for (int i = blockIdx.x * blockDim.x + threadIdx.x; i < EV; i += stride)
        atomicAdd(&g_deg[ei[EV + i]], 1);
}

__global__ void k_finish_deg() {
    int i = blockIdx.x * blockDim.x + threadIdx.x;
    if (i < NV) {
        int d = g_deg[i] + 1;  // + self loop
        g_deg[i] = d;
        g_dinv[i] = rsqrtf((float)d);
    }
}

__global__ __launch_bounds__(1024) void k_scan1() {
    __shared__ int sh[1024];
    int i = blockIdx.x * 1024 + threadIdx.x;
    int v = (i < NV) ? g_deg[i] : 0;
    sh[threadIdx.x] = v;
    __syncthreads();
    for (int off = 1; off < 1024; off <<= 1) {
        int tv = (threadIdx.x >= off) ? sh[threadIdx.x - off] : 0;
        __syncthreads();
        sh[threadIdx.x] += tv;
        __syncthreads();
    }
    if (i < NV) g_rowptr[i] = sh[threadIdx.x] - v;   // exclusive, block-local
    if (threadIdx.x == 1023) g_bsum[blockIdx.x] = sh[1023];
}

__global__ void k_scan2(int nb) {
    if (threadIdx.x == 0) {
        int s = 0;
        for (int i = 0; i < nb; i++) { int v = g_bsum[i]; g_bsum[i] = s; s += v; }
    }
}

__global__ void k_scan3() {
    int i = blockIdx.x * blockDim.x + threadIdx.x;
    if (i < NV) {
        int r = g_rowptr[i] + g_bsum[i >> 10];
        g_rowptr[i] = r;
        g_cursor[i] = r;
    }
    if (i == 0) g_rowptr[NV] = ET;
}

__global__ void k_fill_edges(const int* __restrict__ ei) {
    int stride = gridDim.x * blockDim.x;
    for (int i = blockIdx.x * blockDim.x + threadIdx.x; i < EV; i += stride) {
        int s = ei[i], d = ei[EV + i];
        int pos = atomicAdd(&g_cursor[d], 1);
        g_edge[pos] = make_int2(s, __float_as_int(g_dinv[s] * g_dinv[d]));
    }
}

__global__ void k_fill_self() {
    int i = blockIdx.x * blockDim.x + threadIdx.x;
    if (i < NV) {
        int pos = atomicAdd(&g_cursor[i], 1);
        float di = g_dinv[i];
        g_edge[pos] = make_int2(i, __float_as_int(di * di));
    }
}

// ---------------- diffusion ----------------
__global__ void k_init_h0(const float* __restrict__ x) {
    int i = blockIdx.x * blockDim.x + threadIdx.x;
    if (i >= NV * 32) return;
    float4 xv = reinterpret_cast<const float4*>(x)[i];
    g_h[0][i] = pack_fp8x4(xv.x, xv.y, xv.z, xv.w);
}

__device__ __forceinline__ void acc_edge(float w0, unsigned int u0,
                                         float& sx, float& sy, float& sz, float& sw) {
    float2 lo, hi;
    unpack_fp8x4(u0, lo, hi);
    sx = fmaf(w0, lo.x, sx); sy = fmaf(w0, lo.y, sy);
    sz = fmaf(w0, hi.x, sz); sw = fmaf(w0, hi.y, sw);
}

__global__ __launch_bounds__(256) void k_hop(const unsigned int* __restrict__ hin,
                                             unsigned int* __restrict__ hout) {
    int w = (blockIdx.x * blockDim.x + threadIdx.x) >> 5;
    int lane = threadIdx.x & 31;
    if (w >= NV) return;

    int beg = g_rowptr[w], end = g_rowptr[w + 1];
    float sx = 0.f, sy = 0.f, sz = 0.f, sw = 0.f;
    int j = beg;
    for (; j + 3 < end; j += 4) {
        int2 e0 = g_edge[j], e1 = g_edge[j + 1], e2 = g_edge[j + 2], e3 = g_edge[j + 3];
        unsigned int u0 = __ldg(&hin[e0.x * 32 + lane]);
        unsigned int u1 = __ldg(&hin[e1.x * 32 + lane]);
        unsigned int u2 = __ldg(&hin[e2.x * 32 + lane]);
        unsigned int u3 = __ldg(&hin[e3.x * 32 + lane]);
        acc_edge(__int_as_float(e0.y), u0, sx, sy, sz, sw);
        acc_edge(__int_as_float(e1.y), u1, sx, sy, sz, sw);
        acc_edge(__int_as_float(e2.y), u2, sx, sy, sz, sw);
        acc_edge(__int_as_float(e3.y), u3, sx, sy, sz, sw);
    }
    for (; j < end; j++) {
        int2 e0 = g_edge[j];
        unsigned int u0 = __ldg(&hin[e0.x * 32 + lane]);
        acc_edge(__int_as_float(e0.y), u0, sx, sy, sz, sw);
    }
    hout[w * 32 + lane] = pack_fp8x4(sx, sy, sz, sw);
}

// -------- GEMM1 [N,128]@[128,64] + Taylor combine + attention logits --------
__global__ __launch_bounds__(256) void k_gemm1(const float* __restrict__ x,
                                               const float* __restrict__ t,
                                               const float* __restrict__ W1,
                                               const float* __restrict__ as1,
                                               const float* __restrict__ ad1) {
    __shared__ float sW[64 * 64];     // one K-phase of W1 (16 KB)
    __shared__ float sX[32][132];     // 32 combined node rows, padded
    int tid = threadIdx.x;
    int nb = blockIdx.x * 32;

    // stage: sX[r][4q..4q+3] = sum_k c_k(t) * h_k  (k=0 term from fp32 x)
    for (int i = tid; i < 1024; i += 256) {
        int r = i >> 5, q = i & 31;
        int n = nb + r;
        float4 a = make_float4(0, 0, 0, 0);
        if (n < NV) {
            float4 tv = reinterpret_cast<const float4*>(t)[q];
            float4 cf;
            cf.x = expf(-tv.x); cf.y = expf(-tv.y);
            cf.z = expf(-tv.z); cf.w = expf(-tv.w);
            float4 xv = reinterpret_cast<const float4*>(x)[n * 32 + q];
            a.x = cf.x * xv.x; a.y = cf.y * xv.y;
            a.z = cf.z * xv.z; a.w = cf.w * xv.w;
            #pragma unroll
            for (int k = 1; k <= 10; k++) {
                float inv = 1.f / (float)k;
                cf.x *= tv.x * inv; cf.y *= tv.y * inv;
                cf.z *= tv.z * inv; cf.w *= tv.w * inv;
                unsigned int u = __ldg(&g_h[k][n * 32 + q]);
                float2 lo, hi;
                unpack_fp8x4(u, lo, hi);
                a.x = fmaf(cf.x, lo.x, a.x); a.y = fmaf(cf.y, lo.y, a.y);
                a.z = fmaf(cf.z, hi.x, a.z); a.w = fmaf(cf.w, hi.y, a.w);
            }
        }
        *reinterpret_cast<float4*>(&sX[r][q * 4]) = a;
    }

    int node = tid >> 3, cs = tid & 7;
    float4 a0 = make_float4(0, 0, 0, 0), a1 = make_float4(0, 0, 0, 0);
    for (int ph = 0; ph < 2; ph++) {
        __syncthreads();
        const float4* W4 = reinterpret_cast<const float4*>(W1) + ph * 1024;
        for (int i = tid; i < 1024; i += 256) reinterpret_cast<float4*>(sW)[i] = W4[i];
        __syncthreads();
        #pragma unroll 8
        for (int kk = 0; kk < 64; kk++) {
            float xv = sX[node][ph * 64 + kk];
            float4 w0 = *reinterpret_cast<const float4*>(&sW[kk * 64 + cs * 8]);
            float4 w1 = *reinterpret_cast<const float4*>(&sW[kk * 64 + cs * 8 + 4]);
            a0.x = fmaf(xv, w0.x, a0.x); a0.y = fmaf(xv, w0.y, a0.y);
            a0.z = fmaf(xv, w0.z, a0.z); a0.w = fmaf(xv, w0.w, a0.w);
            a1.x = fmaf(xv, w1.x, a1.x); a1.y = fmaf(xv, w1.y, a1.y);
            a1.z = fmaf(xv, w1.z, a1.z); a1.w = fmaf(xv, w1.w, a1.w);
        }
    }
    int n = nb + node;
    if (n < NV) {
        __half2* p = &g_h1h[n * 32 + cs * 4];
        p[0] = __floats2half2_rn(a0.x, a0.y);
        p[1] = __floats2half2_rn(a0.z, a0.w);
        p[2] = __floats2half2_rn(a1.x, a1.y);
        p[3] = __floats2half2_rn(a1.z, a1.w);
        const float* s8 = as1 + cs * 8;
        const float* d8 = ad1 + cs * 8;
        float ls = a0.x * s8[0] + a0.y * s8[1] + a0.z * s8[2] + a0.w * s8[3]
                 + a1.x * s8[4] + a1.y * s8[5] + a1.z * s8[6] + a1.w * s8[7];
        float ld_ = a0.x * d8[0] + a0.y * d8[1] + a0.z * d8[2] + a0.w * d8[3]
                  + a1.x * d8[4] + a1.y * d8[5] + a1.z * d8[6] + a1.w * d8[7];
        g_als1[n * 8 + cs] = ls;
        g_ald1[n * 8 + cs] = ld_;
    }
}

// ---------------- GAT1: softmax attention + aggregation + bias + ELU ----------------
__global__ __launch_bounds__(256) void k_gat1(const float* __restrict__ b1) {
    int w = (blockIdx.x * blockDim.x + threadIdx.x) >> 5;
    int lane = threadIdx.x & 31;
    if (w >= NV) return;
    int h = lane >> 2, sub = lane & 3;   // lane owns channels h*8 + sub*2 .. +1
    float adn = g_ald1[w * 8 + h];
    int beg = g_rowptr[w], end = g_rowptr[w + 1];

    float mx = -FLT_MAX;
    for (int j = beg + sub; j < end; j += 4) {
        int s = g_edge[j].x;
        float e = g_als1[s * 8 + h] + adn;
        e = (e > 0.f) ? e : 0.2f * e;
        mx = fmaxf(mx, e);
    }
    mx = fmaxf(mx, __shfl_xor_sync(0xffffffffu, mx, 1));
    mx = fmaxf(mx, __shfl_xor_sync(0xffffffffu, mx, 2));

    float den = 0.f, ox = 0.f, oy = 0.f;
    for (int j = beg; j < end; j++) {
        int s = g_edge[j].x;
        float e = g_als1[s * 8 + h] + adn;
        e = (e > 0.f) ? e : 0.2f * e;
        float ex = expf(e - mx);
        den += ex;
        float2 hv = __half22float2(__ldg(&g_h1h[s * 32 + h * 4 + sub]));
        ox = fmaf(ex, hv.x, ox);
        oy = fmaf(ex, hv.y, oy);
    }
    float inv = 1.f / fmaxf(den, 1e-16f);
    int c = h * 8 + sub * 2;
    float v0 = ox * inv + b1[c];
    float v1 = oy * inv + b1[c + 1];
    v0 = (v0 > 0.f) ? v0 : expm1f(v0);
    v1 = (v1 > 0.f) ? v1 : expm1f(v1);
    float* act = reinterpret_cast<float*>(g_act1);
    act[w * 64 + c] = v0;
    act[w * 64 + c + 1] = v1;
}

// ---------------- GEMM2 [N,64]@[64,40] + logits ----------------
__global__ __launch_bounds__(256) void k_gemm2(const float* __restrict__ W2,
                                               const float* __restrict__ as2,
                                               const float* __restrict__ ad2) {
    __shared__ float sW[64 * 40];
    __shared__ float sX[32][68];
    int tid = threadIdx.x;
    int nb = blockIdx.x * 32;
    for (int i = tid; i < 2560; i += 256) sW[i] = W2[i];
    for (int i = tid; i < 512; i += 256) {
        int r = i >> 4, q = i & 15;
        int n = nb + r;
        float4 v = (n < NV) ? g_act1[n * 16 + q] : make_float4(0, 0, 0, 0);
        *reinterpret_cast<float4*>(&sX[r][q * 4]) = v;
    }
    __syncthreads();
    int node = tid >> 3, cs = tid & 7;  // thread owns channels cs*5 .. cs*5+4
    float a[5] = {0, 0, 0, 0, 0};
    #pragma unroll 4
    for (int kk = 0; kk < 64; kk++) {
        float xv = sX[node][kk];
        #pragma unroll
        for (int i = 0; i < 5; i++) a[i] = fmaf(xv, sW[kk * 40 + cs * 5 + i], a[i]);
    }
    int n = nb + node;
    float ps = 0.f, pd = 0.f;
    #pragma unroll
    for (int i = 0; i < 5; i++) { ps += a[i] * as2[cs * 5 + i]; pd += a[i] * ad2[cs * 5 + i]; }
    ps += __shfl_xor_sync(0xffffffffu, ps, 1);
    ps += __shfl_xor_sync(0xffffffffu, ps, 2);
    ps += __shfl_xor_sync(0xffffffffu, ps, 4);
    pd += __shfl_xor_sync(0xffffffffu, pd, 1);
    pd += __shfl_xor_sync(0xffffffffu, pd, 2);
    pd += __shfl_xor_sync(0xffffffffu, pd, 4);
    if (n < NV) {
        #pragma unroll
        for (int i = 0; i < 5; i++) g_h2[n * 40 + cs * 5 + i] = a[i];
        if (cs == 0) { g_als2[n] = ps; g_ald2[n] = pd; }
    }
}

// ---------------- GAT2 + bias + log_softmax -> out ----------------
__global__ __launch_bounds__(256) void k_gat2(const float* __restrict__ b2,
                                              float* __restrict__ out) {
    int w = (blockIdx.x * blockDim.x + threadIdx.x) >> 5;
    int lane = threadIdx.x & 31;
    if (w >= NV) return;
    float adn = g_ald2[w];
    int beg = g_rowptr[w], end = g_rowptr[w + 1];

    float mx = -FLT_MAX;
    for (int j = beg + lane; j < end; j += 32) {
        float e = g_als2[g_edge[j].x] + adn;
        e = (e > 0.f) ? e : 0.2f * e;
        mx = fmaxf(mx, e);
    }
    for (int o = 16; o > 0; o >>= 1) mx = fmaxf(mx, __shfl_xor_sync(0xffffffffu, mx, o));

    float den = 0.f, a0 = 0.f, a1 = 0.f;
    for (int j = beg; j < end; j++) {
        int s = g_edge[j].x;
        float e = g_als2[s] + adn;
        e = (e > 0.f) ? e : 0.2f * e;
        float ex = expf(e - mx);
        den += ex;
        a0 = fmaf(ex, g_h2[s * 40 + lane], a0);
        if (lane < 8) a1 = fmaf(ex, g_h2[s * 40 + 32 + lane], a1);
    }
    float inv = 1.f / fmaxf(den, 1e-16f);
    float v0 = a0 * inv + b2[lane];
    float v1 = (lane < 8) ? (a1 * inv + b2[32 + lane]) : -FLT_MAX;

    float m = fmaxf(v0, v1);
    for (int o = 16; o > 0; o >>= 1) m = fmaxf(m, __shfl_xor_sync(0xffffffffu, m, o));
    float se = expf(v0 - m) + ((lane < 8) ? expf(v1 - m) : 0.f);
    for (int o = 16; o > 0; o >>= 1) se += __shfl_xor_sync(0xffffffffu, se, o);
    float lse = logf(se);
    out[w * 40 + lane] = v0 - m - lse;
    if (lane < 8) out[w * 40 + 32 + lane] = v1 - m - lse;
}

// ---------------- launch ----------------
extern "C" void kernel_launch(void* const* d_in, const int* in_sizes, int n_in,
                              void* d_out, int out_size) {
    const float* x   = (const float*)d_in[0];
    const int*   ei  = (const int*)d_in[1];
    const float* t   = (const float*)d_in[2];
    const float* W1  = (const float*)d_in[3];
    const float* as1 = (const float*)d_in[4];
    const float* ad1 = (const float*)d_in[5];
    const float* b1  = (const float*)d_in[6];
    const float* W2  = (const float*)d_in[7];
    const float* as2 = (const float*)d_in[8];
    const float* ad2 = (const float*)d_in[9];
    const float* b2  = (const float*)d_in[10];
    float* out = (float*)d_out;

    const int NB  = (NV + 255) / 256;          // node-parallel blocks
    const int NWB = (NV * 32 + 255) / 256;     // warp-per-node blocks (12500)
    const int SB  = (NV + 1023) / 1024;        // scan blocks (98)

    // CSR build
    k_zero_deg<<<NB, 256>>>();
    k_count<<<2048, 256>>>(ei);
    k_finish_deg<<<NB, 256>>>();
    k_scan1<<<SB, 1024>>>();
    k_scan2<<<1, 32>>>(SB);
    k_scan3<<<NB, 256>>>();
    k_fill_edges<<<2048, 256>>>(ei);
    k_fill_self<<<NB, 256>>>();

    // diffusion hops: h_k = A_hat h_{k-1}, features in fp8 e4m3
    k_init_h0<<<NWB, 256>>>(x);
    unsigned int* hbase;
    cudaGetSymbolAddress((void**)&hbase, g_h);
    for (int k = 1; k <= 10; k++)
        k_hop<<<NWB, 256>>>(hbase + (size_t)(k - 1) * NV * 32,
                            hbase + (size_t)k * NV * 32);

    // GAT layer 1 (Taylor combine fused into staging)
    k_gemm1<<<(NV + 31) / 32, 256>>>(x, t, W1, as1, ad1);
    k_gat1<<<NWB, 256>>>(b1);

    // GAT layer 2 + log_softmax
    k_gemm2<<<(NV + 31) / 32, 256>>>(W2, as2, ad2);
    k_gat2<<<NWB, 256>>>(b2, out);
}